// round 3
// baseline (speedup 1.0000x reference)
#include <cuda_runtime.h>
#include <cstdint>

#define FDIM 512
#define MT 128          // rows per CTA
#define NT 64           // g-columns per chunk
#define KT 16           // k-slab
#define XS_LD 20        // x smem row pitch (floats), conflict-free + 16B aligned
#define QS_LD 72        // Q smem row pitch (floats), conflict-free + 16B aligned

// round-to-nearest tf32 split: v ~= hi + lo, both exactly representable in tf32
__device__ __forceinline__ void split_tf32(float v, uint32_t& hi, uint32_t& lo) {
    asm("cvt.rna.tf32.f32 %0, %1;" : "=r"(hi) : "f"(v));
    float l = v - __uint_as_float(hi);
    asm("cvt.rna.tf32.f32 %0, %1;" : "=r"(lo) : "f"(l));
}

__device__ __forceinline__ void mma_tf32(float* c, const uint32_t* a, const uint32_t* b) {
    asm volatile(
        "mma.sync.aligned.m16n8k8.row.col.f32.tf32.tf32.f32 "
        "{%0,%1,%2,%3}, {%4,%5,%6,%7}, {%8,%9}, {%0,%1,%2,%3};"
        : "+f"(c[0]), "+f"(c[1]), "+f"(c[2]), "+f"(c[3])
        : "r"(a[0]), "r"(a[1]), "r"(a[2]), "r"(a[3]), "r"(b[0]), "r"(b[1]));
}

#define CP_ASYNC16(dst_u32, src_ptr) \
    asm volatile("cp.async.ca.shared.global [%0], [%1], 16;" :: "r"(dst_u32), "l"(src_ptr))

#define CP_COMMIT() asm volatile("cp.async.commit_group;" ::: "memory")

// x slab: MT x KT floats = 128*16 = 2048 -> 512 float4 -> 2 per thread (256 threads)
#define LOAD_X(k0, bf) do {                                                        \
    _Pragma("unroll")                                                              \
    for (int _i = 0; _i < 2; _i++) {                                               \
        int _idx = tid + 256 * _i;                                                 \
        int _r = _idx >> 2;                                                        \
        int _c = (_idx & 3) << 2;                                                  \
        const float* _src = x + (row0 + (size_t)_r) * FDIM + (k0) + _c;            \
        uint32_t _d = (uint32_t)__cvta_generic_to_shared(&xs[bf][_r * XS_LD + _c]);\
        CP_ASYNC16(_d, _src);                                                      \
    }                                                                              \
} while (0)

// Q slab: KT x NT floats = 16*64 = 1024 -> 256 float4 -> 1 per thread
#define LOAD_Q(k0, n0_, bf) do {                                                   \
    int _r = tid >> 4;                                                             \
    int _c = (tid & 15) << 2;                                                      \
    const float* _src = Q + (size_t)((k0) + _r) * FDIM + (n0_) + _c;               \
    uint32_t _d = (uint32_t)__cvta_generic_to_shared(&qs[bf][_r * QS_LD + _c]);    \
    CP_ASYNC16(_d, _src);                                                          \
} while (0)

__global__ void __launch_bounds__(256) bilinear_tf32_kernel(
    const float* __restrict__ x, const float* __restrict__ Q,
    float* __restrict__ out)
{
    __shared__ __align__(16) float xs[2][MT * XS_LD];
    __shared__ __align__(16) float qs[2][KT * QS_LD];
    __shared__ float red[2][MT];

    const int tid  = threadIdx.x;
    const int lane = tid & 31;
    const int warp = tid >> 5;
    const int wm   = warp & 3;   // 4 warps along M (32 rows each)
    const int wn   = warp >> 2;  // 2 warps along N (32 cols each)
    const int grp  = lane >> 2;  // 0..7
    const int tig  = lane & 3;   // 0..3
    const size_t row0 = (size_t)blockIdx.x * MT;

    float rs[4] = {0.f, 0.f, 0.f, 0.f};  // per-thread row partial sums

    const int NS = FDIM / KT;  // 32 k-slabs

    for (int n0 = 0; n0 < FDIM; n0 += NT) {
        float c[2][4][4];
        #pragma unroll
        for (int mf = 0; mf < 2; mf++)
            #pragma unroll
            for (int nf = 0; nf < 4; nf++)
                #pragma unroll
                for (int i = 0; i < 4; i++) c[mf][nf][i] = 0.f;

        // prologue: slabs 0 and 1 in flight
        LOAD_X(0, 0);  LOAD_Q(0, n0, 0);  CP_COMMIT();
        LOAD_X(KT, 1); LOAD_Q(KT, n0, 1); CP_COMMIT();

        for (int s = 0; s < NS; s++) {
            if (s < NS - 1) asm volatile("cp.async.wait_group 1;" ::: "memory");
            else            asm volatile("cp.async.wait_group 0;" ::: "memory");
            __syncthreads();

            const float* xb = xs[s & 1];
            const float* qb = qs[s & 1];

            #pragma unroll
            for (int ks = 0; ks < KT; ks += 8) {
                uint32_t ah[2][4], al[2][4];
                #pragma unroll
                for (int mf = 0; mf < 2; mf++) {
                    int rb = wm * 32 + mf * 16;
                    float a0 = xb[(rb + grp)     * XS_LD + ks + tig];
                    float a1 = xb[(rb + grp + 8) * XS_LD + ks + tig];
                    float a2 = xb[(rb + grp)     * XS_LD + ks + tig + 4];
                    float a3 = xb[(rb + grp + 8) * XS_LD + ks + tig + 4];
                    split_tf32(a0, ah[mf][0], al[mf][0]);
                    split_tf32(a1, ah[mf][1], al[mf][1]);
                    split_tf32(a2, ah[mf][2], al[mf][2]);
                    split_tf32(a3, ah[mf][3], al[mf][3]);
                }
                uint32_t bh[4][2], bl[4][2];
                #pragma unroll
                for (int nf = 0; nf < 4; nf++) {
                    int col = wn * 32 + nf * 8 + grp;
                    float b0 = qb[(ks + tig)     * QS_LD + col];
                    float b1 = qb[(ks + tig + 4) * QS_LD + col];
                    split_tf32(b0, bh[nf][0], bl[nf][0]);
                    split_tf32(b1, bh[nf][1], bl[nf][1]);
                }
                #pragma unroll
                for (int mf = 0; mf < 2; mf++)
                    #pragma unroll
                    for (int nf = 0; nf < 4; nf++) {
                        mma_tf32(c[mf][nf], ah[mf], bh[nf]);  // hi*hi
                        mma_tf32(c[mf][nf], al[mf], bh[nf]);  // lo*hi
                        mma_tf32(c[mf][nf], ah[mf], bl[nf]);  // hi*lo
                    }
            }
            __syncthreads();

            if (s + 2 < NS) {
                int k0 = (s + 2) * KT;
                LOAD_X(k0, s & 1);
                LOAD_Q(k0, n0, s & 1);
                CP_COMMIT();
            }
        }

        // fused epilogue: out[b] partial += sum_g y[b,g] * x[b,g] over this n-chunk
        #pragma unroll
        for (int mf = 0; mf < 2; mf++) {
            #pragma unroll
            for (int rh = 0; rh < 2; rh++) {
                size_t r = row0 + wm * 32 + mf * 16 + rh * 8 + grp;
                float sum = 0.f;
                #pragma unroll
                for (int nf = 0; nf < 4; nf++) {
                    int col = n0 + wn * 32 + nf * 8 + tig * 2;
                    float xv0 = x[r * FDIM + col];
                    float xv1 = x[r * FDIM + col + 1];
                    sum += c[mf][nf][rh * 2 + 0] * xv0
                         + c[mf][nf][rh * 2 + 1] * xv1;
                }
                rs[mf * 2 + rh] += sum;
            }
        }
    }

    // reduce across the 4 lanes of each group (they hold disjoint columns)
    #pragma unroll
    for (int i = 0; i < 4; i++) {
        rs[i] += __shfl_xor_sync(0xffffffffu, rs[i], 1);
        rs[i] += __shfl_xor_sync(0xffffffffu, rs[i], 2);
    }
    // cross-warp (wn) reduce via smem
    if (tig == 0) {
        #pragma unroll
        for (int mf = 0; mf < 2; mf++)
            #pragma unroll
            for (int rh = 0; rh < 2; rh++)
                red[wn][wm * 32 + mf * 16 + rh * 8 + grp] = rs[mf * 2 + rh];
    }
    __syncthreads();
    if (tid < MT)
        out[row0 + tid] = red[0][tid] + red[1][tid];
}

extern "C" void kernel_launch(void* const* d_in, const int* in_sizes, int n_in,
                              void* d_out, int out_size) {
    const float* x = (const float*)d_in[0];
    const float* Q = (const float*)d_in[1];
    float* out = (float*)d_out;

    int rows = in_sizes[0] / FDIM;       // 131072
    int grid = rows / MT;                // 1024
    bilinear_tf32_kernel<<<grid, 256>>>(x, Q, out);
}

// round 4
// speedup vs baseline: 1.0036x; 1.0036x over previous
#include <cuda_runtime.h>
#include <cstdint>

#define FDIM 512
#define MT 128          // rows per CTA
#define NT 64           // g-columns per chunk
#define KT 16           // k-slab
#define XS_LD 20        // x smem row pitch (floats), conflict-free + 16B aligned
#define QS_LD 72        // Q smem row pitch (floats), conflict-free + 16B aligned

// round-to-nearest tf32 split: v ~= hi + lo, both exactly representable in tf32
__device__ __forceinline__ void split_tf32(float v, uint32_t& hi, uint32_t& lo) {
    asm("cvt.rna.tf32.f32 %0, %1;" : "=r"(hi) : "f"(v));
    float l = v - __uint_as_float(hi);
    asm("cvt.rna.tf32.f32 %0, %1;" : "=r"(lo) : "f"(l));
}

__device__ __forceinline__ void mma_tf32(float* c, const uint32_t* a, const uint32_t* b) {
    asm volatile(
        "mma.sync.aligned.m16n8k8.row.col.f32.tf32.tf32.f32 "
        "{%0,%1,%2,%3}, {%4,%5,%6,%7}, {%8,%9}, {%0,%1,%2,%3};"
        : "+f"(c[0]), "+f"(c[1]), "+f"(c[2]), "+f"(c[3])
        : "r"(a[0]), "r"(a[1]), "r"(a[2]), "r"(a[3]), "r"(b[0]), "r"(b[1]));
}

#define CP_ASYNC16(dst_u32, src_ptr) \
    asm volatile("cp.async.ca.shared.global [%0], [%1], 16;" :: "r"(dst_u32), "l"(src_ptr))

#define CP_COMMIT() asm volatile("cp.async.commit_group;" ::: "memory")

// x slab: MT x KT floats = 128*16 = 2048 -> 512 float4 -> 2 per thread (256 threads)
#define LOAD_X(k0, bf) do {                                                        \
    _Pragma("unroll")                                                              \
    for (int _i = 0; _i < 2; _i++) {                                               \
        int _idx = tid + 256 * _i;                                                 \
        int _r = _idx >> 2;                                                        \
        int _c = (_idx & 3) << 2;                                                  \
        const float* _src = x + (row0 + (size_t)_r) * FDIM + (k0) + _c;            \
        uint32_t _d = (uint32_t)__cvta_generic_to_shared(&xs[bf][_r * XS_LD + _c]);\
        CP_ASYNC16(_d, _src);                                                      \
    }                                                                              \
} while (0)

// Q slab: KT x NT floats = 16*64 = 1024 -> 256 float4 -> 1 per thread
#define LOAD_Q(k0, n0_, bf) do {                                                   \
    int _r = tid >> 4;                                                             \
    int _c = (tid & 15) << 2;                                                      \
    const float* _src = Q + (size_t)((k0) + _r) * FDIM + (n0_) + _c;               \
    uint32_t _d = (uint32_t)__cvta_generic_to_shared(&qs[bf][_r * QS_LD + _c]);    \
    CP_ASYNC16(_d, _src);                                                          \
} while (0)

__global__ void __launch_bounds__(256) bilinear_tf32_kernel(
    const float* __restrict__ x, const float* __restrict__ Q,
    float* __restrict__ out)
{
    __shared__ __align__(16) float xs[2][MT * XS_LD];
    __shared__ __align__(16) float qs[2][KT * QS_LD];
    __shared__ float red[2][MT];

    const int tid  = threadIdx.x;
    const int lane = tid & 31;
    const int warp = tid >> 5;
    const int wm   = warp & 3;   // 4 warps along M (32 rows each)
    const int wn   = warp >> 2;  // 2 warps along N (32 cols each)
    const int grp  = lane >> 2;  // 0..7
    const int tig  = lane & 3;   // 0..3
    const size_t row0 = (size_t)blockIdx.x * MT;

    float rs[4] = {0.f, 0.f, 0.f, 0.f};  // per-thread row partial sums

    const int NS = FDIM / KT;  // 32 k-slabs

    for (int n0 = 0; n0 < FDIM; n0 += NT) {
        float c[2][4][4];
        #pragma unroll
        for (int mf = 0; mf < 2; mf++)
            #pragma unroll
            for (int nf = 0; nf < 4; nf++)
                #pragma unroll
                for (int i = 0; i < 4; i++) c[mf][nf][i] = 0.f;

        // prologue: slabs 0 and 1 in flight
        LOAD_X(0, 0);  LOAD_Q(0, n0, 0);  CP_COMMIT();
        LOAD_X(KT, 1); LOAD_Q(KT, n0, 1); CP_COMMIT();

        for (int s = 0; s < NS; s++) {
            if (s < NS - 1) asm volatile("cp.async.wait_group 1;" ::: "memory");
            else            asm volatile("cp.async.wait_group 0;" ::: "memory");
            __syncthreads();

            const float* xb = xs[s & 1];
            const float* qb = qs[s & 1];

            #pragma unroll
            for (int ks = 0; ks < KT; ks += 8) {
                uint32_t ah[2][4], al[2][4];
                #pragma unroll
                for (int mf = 0; mf < 2; mf++) {
                    int rb = wm * 32 + mf * 16;
                    float a0 = xb[(rb + grp)     * XS_LD + ks + tig];
                    float a1 = xb[(rb + grp + 8) * XS_LD + ks + tig];
                    float a2 = xb[(rb + grp)     * XS_LD + ks + tig + 4];
                    float a3 = xb[(rb + grp + 8) * XS_LD + ks + tig + 4];
                    split_tf32(a0, ah[mf][0], al[mf][0]);
                    split_tf32(a1, ah[mf][1], al[mf][1]);
                    split_tf32(a2, ah[mf][2], al[mf][2]);
                    split_tf32(a3, ah[mf][3], al[mf][3]);
                }
                uint32_t bh[4][2], bl[4][2];
                #pragma unroll
                for (int nf = 0; nf < 4; nf++) {
                    int col = wn * 32 + nf * 8 + grp;
                    float b0 = qb[(ks + tig)     * QS_LD + col];
                    float b1 = qb[(ks + tig + 4) * QS_LD + col];
                    split_tf32(b0, bh[nf][0], bl[nf][0]);
                    split_tf32(b1, bh[nf][1], bl[nf][1]);
                }
                #pragma unroll
                for (int mf = 0; mf < 2; mf++)
                    #pragma unroll
                    for (int nf = 0; nf < 4; nf++) {
                        mma_tf32(c[mf][nf], ah[mf], bh[nf]);  // hi*hi
                        mma_tf32(c[mf][nf], al[mf], bh[nf]);  // lo*hi
                        mma_tf32(c[mf][nf], ah[mf], bl[nf]);  // hi*lo
                    }
            }
            __syncthreads();

            if (s + 2 < NS) {
                int k0 = (s + 2) * KT;
                LOAD_X(k0, s & 1);
                LOAD_Q(k0, n0, s & 1);
                CP_COMMIT();
            }
        }

        // fused epilogue: out[b] partial += sum_g y[b,g] * x[b,g] over this n-chunk
        #pragma unroll
        for (int mf = 0; mf < 2; mf++) {
            #pragma unroll
            for (int rh = 0; rh < 2; rh++) {
                size_t r = row0 + wm * 32 + mf * 16 + rh * 8 + grp;
                float sum = 0.f;
                #pragma unroll
                for (int nf = 0; nf < 4; nf++) {
                    int col = n0 + wn * 32 + nf * 8 + tig * 2;
                    float xv0 = x[r * FDIM + col];
                    float xv1 = x[r * FDIM + col + 1];
                    sum += c[mf][nf][rh * 2 + 0] * xv0
                         + c[mf][nf][rh * 2 + 1] * xv1;
                }
                rs[mf * 2 + rh] += sum;
            }
        }
    }

    // reduce across the 4 lanes of each group (they hold disjoint columns)
    #pragma unroll
    for (int i = 0; i < 4; i++) {
        rs[i] += __shfl_xor_sync(0xffffffffu, rs[i], 1);
        rs[i] += __shfl_xor_sync(0xffffffffu, rs[i], 2);
    }
    // cross-warp (wn) reduce via smem
    if (tig == 0) {
        #pragma unroll
        for (int mf = 0; mf < 2; mf++)
            #pragma unroll
            for (int rh = 0; rh < 2; rh++)
                red[wn][wm * 32 + mf * 16 + rh * 8 + grp] = rs[mf * 2 + rh];
    }
    __syncthreads();
    if (tid < MT)
        out[row0 + tid] = red[0][tid] + red[1][tid];
}

extern "C" void kernel_launch(void* const* d_in, const int* in_sizes, int n_in,
                              void* d_out, int out_size) {
    const float* x = (const float*)d_in[0];
    const float* Q = (const float*)d_in[1];
    float* out = (float*)d_out;

    int rows = in_sizes[0] / FDIM;       // 131072
    int grid = rows / MT;                // 1024
    bilinear_tf32_kernel<<<grid, 256>>>(x, Q, out);
}